// round 9
// baseline (speedup 1.0000x reference)
#include <cuda_runtime.h>

typedef unsigned long long ull;

#define THREADS 512
#define SMEM_FLOATS 57344             // dup table: 3 quad arrays + 1 pair array
#define SMEM_BYTES  (SMEM_FLOATS * 4) // 229376 B (staging reuses this after mainloop)

__device__ __forceinline__ ull pack2(float lo, float hi) {
    ull r; asm("mov.b64 %0, {%1, %2};" : "=l"(r) : "f"(lo), "f"(hi)); return r;
}
__device__ __forceinline__ void unpack2(ull v, float& lo, float& hi) {
    asm("mov.b64 {%0, %1}, %2;" : "=f"(lo), "=f"(hi) : "l"(v));
}
__device__ __forceinline__ ull mul2(ull a, ull b) {
    ull d; asm("mul.rn.f32x2 %0, %1, %2;" : "=l"(d) : "l"(a), "l"(b)); return d;
}
__device__ __forceinline__ ull fma2(ull a, ull b, ull c) {
    ull d; asm("fma.rn.f32x2 %0, %1, %2, %3;" : "=l"(d) : "l"(a), "l"(b), "l"(c)); return d;
}

// ANFIS:
//   den[b] = prod_i (sum_t mu[b,i,t])
//   G[b,j] = sum_r w[b,r] * C[r,j]  (hierarchical base-4 partial products)
//   out[b] = (sum_j xa[b,j] * G[b,j]) / (den[b] + 1e-8)
// f32x2 packs ELEMENT PAIRS; each thread carries 4 elements (pairs P, Q).
// Coefficients live in SMEM PRE-DUPLICATED: Q0[r]=(c0,c0,c1,c1),
// Q1[r]=(c2,c2,c3,c3), Q2[r]=(c4,c4,c5,c5), P6[r]=(c6,c6) -> every LDS.128
// yields two ready f32x2 operands, no register duplication MOVs.
// 16 warps/block = 8 rule-octants (fixed d0, half of d1) x 2 quad-groups.
// Octant partials are combined by REUSING the table smem after the mainloop.
__global__ void __launch_bounds__(THREADS, 1) anfis_kernel(
    const float* __restrict__ x,
    const float* __restrict__ centers,
    const float* __restrict__ sigmas,
    const float* __restrict__ cons,
    float* __restrict__ out)
{
    extern __shared__ float sm[];

    // --- Build duplicated table ---
    for (int idx = threadIdx.x; idx < 4096 * 7; idx += THREADS) {
        int r = idx / 7;
        int j = idx - r * 7;
        float v = cons[idx];
        float* dst;
        if (j < 6) dst = sm + ((j >> 1) << 14) + r * 4 + ((j & 1) << 1);
        else       dst = sm + 49152 + r * 2;
        dst[0] = v;
        dst[1] = v;
    }

    int lane = threadIdx.x & 31;
    int warp = threadIdx.x >> 5;
    int g    = warp & 1;            // quad group
    int rs   = warp >> 1;           // rule octant 0..7
    int d0   = rs >> 1;
    int d1h  = rs & 1;
    int quad = g * 32 + lane;       // 0..63
    int q    = blockIdx.x * 64 + quad;

    int b0 = q, b1 = q + 8192, b2 = q + 16384, b3 = q + 24576;

    // --- Memberships for 4 elements; pairs P=(b0,b1), Q=(b2,b3) ---
    float xv0[6], xv1[6], xv2[6], xv3[6];
#pragma unroll
    for (int i = 0; i < 6; i++) {
        xv0[i] = x[b0 * 6 + i];
        xv1[i] = x[b1 * 6 + i];
        xv2[i] = x[b2 * 6 + i];
        xv3[i] = x[b3 * 6 + i];
    }

    ull A0P = 0, A0Q = 0;
    ull m1P[2], m1Q[2];
    ull m2P[4], m2Q[4], m3P[4], m3Q[4], m4P[4], m4Q[4], m5P[4], m5Q[4];
    float den0 = 1.0f, den1 = 1.0f, den2 = 1.0f, den3 = 1.0f;

#pragma unroll
    for (int i = 0; i < 6; i++) {
        float s0 = 0.0f, s1 = 0.0f, s2 = 0.0f, s3 = 0.0f;
#pragma unroll
        for (int t = 0; t < 4; t++) {
            float c   = centers[i * 4 + t];
            float sg  = fabsf(sigmas[i * 4 + t]) + 1e-6f;
            float inv = 0.5f / (sg * sg);
            float e0 = xv0[i] - c, e1 = xv1[i] - c, e2 = xv2[i] - c, e3 = xv3[i] - c;
            float v0 = __expf(-e0 * e0 * inv);
            float v1 = __expf(-e1 * e1 * inv);
            float v2 = __expf(-e2 * e2 * inv);
            float v3 = __expf(-e3 * e3 * inv);
            s0 += v0; s1 += v1; s2 += v2; s3 += v3;
            ull P = pack2(v0, v1);
            ull Q = pack2(v2, v3);
            if (i == 0) { if (t == d0) { A0P = P; A0Q = Q; } }
            else if (i == 1) {
                if (t == d1h * 2)     { m1P[0] = P; m1Q[0] = Q; }
                if (t == d1h * 2 + 1) { m1P[1] = P; m1Q[1] = Q; }
            }
            else if (i == 2) { m2P[t] = P; m2Q[t] = Q; }
            else if (i == 3) { m3P[t] = P; m3Q[t] = Q; }
            else if (i == 4) { m4P[t] = P; m4Q[t] = Q; }
            else             { m5P[t] = P; m5Q[t] = Q; }
        }
        den0 *= s0; den1 *= s1; den2 *= s2; den3 *= s3;
    }
    __syncthreads();

    const ulonglong2* Q0 = (const ulonglong2*)(sm);
    const ulonglong2* Q1 = (const ulonglong2*)(sm + 16384);
    const ulonglong2* Q2 = (const ulonglong2*)(sm + 32768);
    const ull*        P6 = (const ull*)(sm + 49152);

    ull accP[7], accQ[7];
#pragma unroll
    for (int j = 0; j < 7; j++) { accP[j] = 0; accQ[j] = 0; }

#pragma unroll 1
    for (int d1i = 0; d1i < 2; d1i++) {
        ull A1P = mul2(A0P, m1P[d1i]);
        ull A1Q = mul2(A0Q, m1Q[d1i]);
        int d1 = d1h * 2 + d1i;
#pragma unroll 1
        for (int d2 = 0; d2 < 4; d2++) {
            ull A2P = mul2(A1P, m2P[d2]);
            ull A2Q = mul2(A1Q, m2Q[d2]);
            int rbase = d0 * 1024 + d1 * 256 + d2 * 64;
#pragma unroll
            for (int d3 = 0; d3 < 4; d3++) {
                ull A3P = mul2(A2P, m3P[d3]);
                ull A3Q = mul2(A2Q, m3Q[d3]);
#pragma unroll
                for (int d4 = 0; d4 < 4; d4++) {
                    ull A4P = mul2(A3P, m4P[d4]);
                    ull A4Q = mul2(A3Q, m4Q[d4]);
                    int rr = rbase + d3 * 16 + d4 * 4;
#pragma unroll
                    for (int d5 = 0; d5 < 4; d5++) {
                        ull wP = mul2(A4P, m5P[d5]);
                        ull wQ = mul2(A4Q, m5Q[d5]);
                        int r = rr + d5;
                        ulonglong2 q0 = Q0[r];
                        ulonglong2 q1 = Q1[r];
                        ulonglong2 q2 = Q2[r];
                        ull        p6 = P6[r];
                        accP[0] = fma2(wP, q0.x, accP[0]);
                        accQ[0] = fma2(wQ, q0.x, accQ[0]);
                        accP[1] = fma2(wP, q0.y, accP[1]);
                        accQ[1] = fma2(wQ, q0.y, accQ[1]);
                        accP[2] = fma2(wP, q1.x, accP[2]);
                        accQ[2] = fma2(wQ, q1.x, accQ[2]);
                        accP[3] = fma2(wP, q1.y, accP[3]);
                        accQ[3] = fma2(wQ, q1.y, accQ[3]);
                        accP[4] = fma2(wP, q2.x, accP[4]);
                        accQ[4] = fma2(wQ, q2.x, accQ[4]);
                        accP[5] = fma2(wP, q2.y, accP[5]);
                        accQ[5] = fma2(wQ, q2.y, accQ[5]);
                        accP[6] = fma2(wP, p6, accP[6]);
                        accQ[6] = fma2(wQ, p6, accQ[6]);
                    }
                }
            }
        }
    }

    // --- Octant combine: REUSE table smem as staging (all reads are done) ---
    __syncthreads();
    if (rs != 0) {
        float* base = sm + ((rs - 1) * 64 + quad) * 29;
#pragma unroll
        for (int j = 0; j < 7; j++) {
            float a, bf, c2, d2v;
            unpack2(accP[j], a, bf);
            unpack2(accQ[j], c2, d2v);
            base[j * 4 + 0] = a;
            base[j * 4 + 1] = bf;
            base[j * 4 + 2] = c2;
            base[j * 4 + 3] = d2v;
        }
    }
    __syncthreads();

    if (rs == 0) {
        float g0[7], g1[7], g2[7], g3[7];
#pragma unroll
        for (int j = 0; j < 7; j++) {
            unpack2(accP[j], g0[j], g1[j]);
            unpack2(accQ[j], g2[j], g3[j]);
        }
#pragma unroll 1
        for (int o = 0; o < 7; o++) {
            const float* base = sm + (o * 64 + quad) * 29;
#pragma unroll
            for (int j = 0; j < 7; j++) {
                g0[j] += base[j * 4 + 0];
                g1[j] += base[j * 4 + 1];
                g2[j] += base[j * 4 + 2];
                g3[j] += base[j * 4 + 3];
            }
        }
        float n0 = g0[6], n1 = g1[6], n2 = g2[6], n3 = g3[6];
#pragma unroll
        for (int i = 0; i < 6; i++) {
            n0 += g0[i] * xv0[i];
            n1 += g1[i] * xv1[i];
            n2 += g2[i] * xv2[i];
            n3 += g3[i] * xv3[i];
        }
        out[b0] = n0 / (den0 + 1e-8f);
        out[b1] = n1 / (den1 + 1e-8f);
        out[b2] = n2 / (den2 + 1e-8f);
        out[b3] = n3 / (den3 + 1e-8f);
    }
}

extern "C" void kernel_launch(void* const* d_in, const int* in_sizes, int n_in,
                              void* d_out, int out_size) {
    const float* x       = (const float*)d_in[0];
    const float* centers = (const float*)d_in[1];
    const float* sigmas  = (const float*)d_in[2];
    const float* cons    = (const float*)d_in[3];
    float* out = (float*)d_out;

    int B = in_sizes[0] / 6;        // 32768
    int blocks = B / 256;           // 128 (64 quads x 4 elements)

    cudaFuncSetAttribute(anfis_kernel,
                         cudaFuncAttributeMaxDynamicSharedMemorySize, SMEM_BYTES);

    anfis_kernel<<<blocks, THREADS, SMEM_BYTES>>>(x, centers, sigmas, cons, out);
}